// round 6
// baseline (speedup 1.0000x reference)
#include <cuda_runtime.h>

#define NN     100000
#define NFEAT  512
#define HID    16
#define NCLASS 40
#define EMAX   3200000

// ---------------- scratch (static device globals; no allocation) ----------------
__device__ int   g_cnt[NN];                 // per-dst edge count
__device__ int   g_off[NN + 1];             // CSR offsets
__device__ int   g_cur[NN];                 // fill cursors
__device__ float g_dinv[NN];
__device__ int   g_es[EMAX];                // CSR payload: src node per slot
__device__ float g_ewc[EMAX];               // CSR payload: edge weight per slot
__device__ float g_W1[NFEAT * 64];          // packed [f][c]: c<32 -> iw1[k=c/16][f][c%16], c>=32 -> rw1
__device__ float g_HR[(size_t)NN * 64];     // [n][c]: c<32 = x@iw1 (k-major), c>=32 = x@rw1
__device__ float g_h1[NN * HID];            // layer-1 output
__device__ float g_agg2[NN * HID];          // layer-2 aggregate (pre-transform)
__device__ float g_W2[HID * 160];           // packed [f][c]: c<80 -> iw2[k][f][c%40], c>=80 -> rw2

// ---------------- setup kernels ----------------
__global__ void zero_kernel() {
    int i = blockIdx.x * blockDim.x + threadIdx.x;
    if (i < NN) g_cnt[i] = 0;
}

__global__ void pack_w1(const float* __restrict__ iw1, const float* __restrict__ rw1) {
    int i = blockIdx.x * blockDim.x + threadIdx.x;
    if (i >= NFEAT * 64) return;
    int f = i >> 6, c = i & 63;
    float v;
    if (c < 32) { int k = c >> 4, j = c & 15; v = iw1[(k * NFEAT + f) * HID + j]; }
    else        { int c2 = c - 32; int k = c2 >> 4, j = c2 & 15; v = rw1[(k * NFEAT + f) * HID + j]; }
    g_W1[i] = v;
}

__global__ void pack_w2(const float* __restrict__ iw2, const float* __restrict__ rw2) {
    int i = blockIdx.x * blockDim.x + threadIdx.x;
    if (i >= HID * 160) return;
    int f = i / 160, c = i % 160;
    float v;
    if (c < 80) { int k = c / 40, o = c % 40; v = iw2[(k * HID + f) * NCLASS + o]; }
    else        { int c2 = c - 80; int k = c2 / 40, o = c2 % 40; v = rw2[(k * HID + f) * NCLASS + o]; }
    g_W2[i] = v;
}

__global__ void count_kernel(const int* __restrict__ dst, int E) {
    int e = blockIdx.x * blockDim.x + threadIdx.x;
    if (e < E) atomicAdd(&g_cnt[__ldg(dst + e)], 1);
}

// Single-block exclusive scan over g_cnt -> g_off (+ copy to g_cur) + dinv
__global__ void scan_kernel() {
    const int T = 1024;
    int t = threadIdx.x;
    int per = (NN + T - 1) / T;              // 98
    int begin = t * per;
    int end = begin + per; if (end > NN) end = NN;
    int s = 0;
    for (int i = begin; i < end; ++i) s += g_cnt[i];
    __shared__ int sh[T];
    sh[t] = s;
    __syncthreads();
    // Hillis-Steele inclusive scan
    for (int off = 1; off < T; off <<= 1) {
        int v = (t >= off) ? sh[t - off] : 0;
        __syncthreads();
        sh[t] += v;
        __syncthreads();
    }
    int run = sh[t] - s;                     // exclusive prefix for this thread's range
    for (int i = begin; i < end; ++i) {
        g_off[i] = run;
        g_cur[i] = run;
        int c = g_cnt[i];
        g_dinv[i] = (c > 0) ? rsqrtf((float)c) : 0.f;
        run += c;
    }
    if (t == T - 1) g_off[NN] = run;
}

__global__ void fill_kernel(const int* __restrict__ src, const int* __restrict__ dst, int E) {
    int e = blockIdx.x * blockDim.x + threadIdx.x;
    if (e >= E) return;
    int s = __ldg(src + e), d = __ldg(dst + e);
    float w = g_dinv[s] * g_dinv[d];
    int pos = atomicAdd(&g_cur[d], 1);
    g_es[pos] = s;
    g_ewc[pos] = w;
}

// ---------------- dense: HR[100000,64] = x[100000,512] @ W1[512,64] ----------------
#define BM 128
#define BN 64
#define BK 16
__global__ void gemm1_kernel(const float* __restrict__ x, int nrows) {
    __shared__ float As[BK][BM + 4];         // [k][m], padded
    __shared__ float Bs[BK][BN];             // [k][n]
    int tid = threadIdx.x;                   // 256 threads
    int tx = tid & 15, ty = tid >> 4;        // 16 x 16
    int brow = blockIdx.x * BM;
    float acc[8][4];
#pragma unroll
    for (int i = 0; i < 8; i++)
#pragma unroll
        for (int j = 0; j < 4; j++) acc[i][j] = 0.f;

    for (int k0 = 0; k0 < NFEAT; k0 += BK) {
#pragma unroll
        for (int it = 0; it < 2; ++it) {     // A: 128x16 = 512 float4
            int q = tid + it * 256;
            int row = q >> 2, c4 = q & 3;
            int gr = brow + row;
            float4 v = make_float4(0.f, 0.f, 0.f, 0.f);
            if (gr < nrows) v = *(const float4*)&x[(size_t)gr * NFEAT + k0 + c4 * 4];
            As[c4 * 4 + 0][row] = v.x;
            As[c4 * 4 + 1][row] = v.y;
            As[c4 * 4 + 2][row] = v.z;
            As[c4 * 4 + 3][row] = v.w;
        }
        {                                     // B: 16x64 = 256 float4
            int row = tid >> 4, c4 = tid & 15;
            *(float4*)&Bs[row][c4 * 4] = *(const float4*)&g_W1[(k0 + row) * 64 + c4 * 4];
        }
        __syncthreads();
#pragma unroll
        for (int kk = 0; kk < BK; ++kk) {
            float a[8], b[4];
            *(float4*)&a[0] = *(const float4*)&As[kk][ty * 8];
            *(float4*)&a[4] = *(const float4*)&As[kk][ty * 8 + 4];
            *(float4*)&b[0] = *(const float4*)&Bs[kk][tx * 4];
#pragma unroll
            for (int i = 0; i < 8; i++)
#pragma unroll
                for (int j = 0; j < 4; j++) acc[i][j] += a[i] * b[j];
        }
        __syncthreads();
    }
#pragma unroll
    for (int i = 0; i < 8; i++) {
        int gr = brow + ty * 8 + i;
        if (gr < nrows)
            *(float4*)&g_HR[(size_t)gr * 64 + tx * 4] =
                make_float4(acc[i][0], acc[i][1], acc[i][2], acc[i][3]);
    }
}

// ---------------- layer-1 pull + epilogue: warp per dst node ----------------
// lane owns column c (0..31, k-major). acc = sum_e w * HR[src][c]; then fused relu/mean.
__global__ void edge1_pull(const float* __restrict__ b1) {
    int warp = (blockIdx.x * blockDim.x + threadIdx.x) >> 5;
    int lane = threadIdx.x & 31;
    if (warp >= NN) return;
    int beg = g_off[warp], end = g_off[warp + 1];
    float acc = 0.f;
    for (int base = beg; base < end; base += 32) {
        int j = base + lane;
        int s = 0; float w = 0.f;
        if (j < end) { s = g_es[j]; w = g_ewc[j]; }
#pragma unroll
        for (int i = 0; i < 32; i++) {
            int   ss = __shfl_sync(0xffffffffu, s, i);
            float ww = __shfl_sync(0xffffffffu, w, i);
            acc += ww * __ldg(&g_HR[(size_t)ss * 64 + lane]);   // ww=0 for padding
        }
    }
    float r = fmaxf(acc + g_HR[(size_t)warp * 64 + 32 + lane] + __ldg(&b1[lane]), 0.f);
    float r2 = __shfl_down_sync(0xffffffffu, r, 16);
    if (lane < 16) g_h1[warp * HID + lane] = 0.5f * (r + r2);
}

// ---------------- layer-2 pull (pre-transform): warp per dst node ----------------
// half-warps process alternating edges; lane owns column c = lane & 15.
__global__ void edge2_pull() {
    int warp = (blockIdx.x * blockDim.x + threadIdx.x) >> 5;
    int lane = threadIdx.x & 31;
    if (warp >= NN) return;
    int c = lane & 15, h = lane >> 4;
    int beg = g_off[warp], end = g_off[warp + 1];
    float acc = 0.f;
    for (int base = beg; base < end; base += 32) {
        int j = base + lane;
        int s = 0; float w = 0.f;
        if (j < end) { s = g_es[j]; w = g_ewc[j]; }
#pragma unroll
        for (int i = 0; i < 16; i++) {
            int idx = 2 * i + h;
            int   ss = __shfl_sync(0xffffffffu, s, idx);
            float ww = __shfl_sync(0xffffffffu, w, idx);
            acc += ww * __ldg(&g_h1[ss * HID + c]);
        }
    }
    acc += __shfl_xor_sync(0xffffffffu, acc, 16);
    if (lane < 16) g_agg2[warp * HID + lane] = acc;
}

// ---------------- layer-2 transform + epilogue ----------------
__global__ void out_kernel(const float* __restrict__ b2, float* __restrict__ out, int nrows) {
    __shared__ float Ws[HID * 160];
    int tid = threadIdx.x;                   // 320 threads: 8 nodes x 40 outputs
    for (int i = tid; i < HID * 160; i += 320) Ws[i] = g_W2[i];
    __syncthreads();
    int n = blockIdx.x * 8 + tid / 40;
    int o = tid - (tid / 40) * 40;
    if (n >= nrows) return;
    float a[HID], hv[HID];
#pragma unroll
    for (int f = 0; f < HID; ++f) {
        a[f]  = g_agg2[n * HID + f];
        hv[f] = g_h1[n * HID + f];
    }
    float acc0 = b2[o], acc1 = b2[40 + o];
#pragma unroll
    for (int f = 0; f < HID; ++f) {
        const float* wr = &Ws[f * 160];
        acc0 += a[f] * wr[o]      + hv[f] * wr[80 + o];
        acc1 += a[f] * wr[40 + o] + hv[f] * wr[120 + o];
    }
    out[n * 40 + o] = 0.5f * (fmaxf(acc0, 0.f) + fmaxf(acc1, 0.f));
}

// ---------------- launch ----------------
extern "C" void kernel_launch(void* const* d_in, const int* in_sizes, int n_in,
                              void* d_out, int out_size) {
    const float* x   = (const float*)d_in[0];
    const int*   ei  = (const int*)d_in[1];
    const float* iw1 = (const float*)d_in[2];
    const float* rw1 = (const float*)d_in[3];
    const float* b1  = (const float*)d_in[4];
    const float* iw2 = (const float*)d_in[5];
    const float* rw2 = (const float*)d_in[6];
    const float* b2  = (const float*)d_in[7];
    float* out = (float*)d_out;

    int E = in_sizes[1] / 2;
    const int* src = ei;
    const int* dst = ei + E;

    zero_kernel<<<(NN + 255) / 256, 256>>>();
    pack_w1<<<(NFEAT * 64 + 255) / 256, 256>>>(iw1, rw1);
    pack_w2<<<(HID * 160 + 255) / 256, 256>>>(iw2, rw2);
    count_kernel<<<(E + 255) / 256, 256>>>(dst, E);
    scan_kernel<<<1, 1024>>>();
    fill_kernel<<<(E + 255) / 256, 256>>>(src, dst, E);
    gemm1_kernel<<<(NN + BM - 1) / BM, 256>>>(x, NN);
    edge1_pull<<<(NN * 32 + 255) / 256, 256>>>(b1);
    edge2_pull<<<(NN * 32 + 255) / 256, 256>>>();
    out_kernel<<<(NN + 7) / 8, 320>>>(b2, out, NN);
}

// round 13
// speedup vs baseline: 2.0838x; 2.0838x over previous
#include <cuda_runtime.h>
#include <cstdint>

#define NN     100000
#define NFEAT  512
#define HID    16
#define NCLASS 40
#define EMAX   3200000

// ---------------- scratch (static device globals; no allocation) ----------------
__device__ float g_deg[NN];
__device__ float g_dinv[NN];
__device__ float g_ew[EMAX];
__device__ float g_W1[NFEAT * 64];          // packed [f][c]: c<32 -> iw1[k=c/16][f][c%16], c>=32 -> rw1
__device__ float g_HR[(size_t)NN * 64];     // [n][c]: c<32 = x@iw1 (k-major), c>=32 = x@rw1
__device__ float g_agg1[(size_t)NN * 32];   // scatter target layer 1
__device__ float g_h1[NN * HID];            // layer-1 output
__device__ float g_agg2[NN * HID];          // scatter target layer 2 (pre-transform)
__device__ float g_W2[HID * 160];           // packed [f][c]: c<80 -> iw2[k][f][c%40], c>=80 -> rw2

// ---------------- helpers ----------------
__device__ __forceinline__ void red_add_v4(float* p, float a, float b, float c, float d) {
    asm volatile("red.global.add.v4.f32 [%0], {%1,%2,%3,%4};"
                 :: "l"(p), "f"(a), "f"(b), "f"(c), "f"(d) : "memory");
}
__device__ __forceinline__ unsigned long long pack_dup(float a) {
    unsigned long long r;
    uint32_t u = __float_as_uint(a);
    asm("mov.b64 %0, {%1, %2};" : "=l"(r) : "r"(u), "r"(u));
    return r;
}
__device__ __forceinline__ void fma2(unsigned long long& acc, unsigned long long a,
                                     unsigned long long b) {
    asm("fma.rn.f32x2 %0, %1, %2, %0;" : "+l"(acc) : "l"(a), "l"(b));
}
__device__ __forceinline__ float2 unpack2(unsigned long long v) {
    uint32_t lo, hi;
    asm("mov.b64 {%0, %1}, %2;" : "=r"(lo), "=r"(hi) : "l"(v));
    return make_float2(__uint_as_float(lo), __uint_as_float(hi));
}

// ---------------- setup kernels ----------------
__global__ void zero_kernel() {
    int i = blockIdx.x * blockDim.x + threadIdx.x;
    if (i < NN) g_deg[i] = 0.f;
    if (i < NN * 32) g_agg1[i] = 0.f;
    if (i < NN * 16) g_agg2[i] = 0.f;
}

__global__ void pack_w1(const float* __restrict__ iw1, const float* __restrict__ rw1) {
    int i = blockIdx.x * blockDim.x + threadIdx.x;
    if (i >= NFEAT * 64) return;
    int f = i >> 6, c = i & 63;
    float v;
    if (c < 32) { int k = c >> 4, j = c & 15; v = iw1[(k * NFEAT + f) * HID + j]; }
    else        { int c2 = c - 32; int k = c2 >> 4, j = c2 & 15; v = rw1[(k * NFEAT + f) * HID + j]; }
    g_W1[i] = v;
}

__global__ void pack_w2(const float* __restrict__ iw2, const float* __restrict__ rw2) {
    int i = blockIdx.x * blockDim.x + threadIdx.x;
    if (i >= HID * 160) return;
    int f = i / 160, c = i % 160;
    float v;
    if (c < 80) { int k = c / 40, o = c % 40; v = iw2[(k * HID + f) * NCLASS + o]; }
    else        { int c2 = c - 80; int k = c2 / 40, o = c2 % 40; v = rw2[(k * HID + f) * NCLASS + o]; }
    g_W2[i] = v;
}

__global__ void deg_kernel(const int* __restrict__ dst, int E) {
    int e = blockIdx.x * blockDim.x + threadIdx.x;
    if (e < E) atomicAdd(&g_deg[__ldg(dst + e)], 1.0f);
}

__global__ void dinv_kernel() {
    int n = blockIdx.x * blockDim.x + threadIdx.x;
    if (n < NN) { float d = g_deg[n]; g_dinv[n] = (d > 0.f) ? rsqrtf(d) : 0.f; }
}

__global__ void ew_kernel(const int* __restrict__ src, const int* __restrict__ dst, int E) {
    int e = blockIdx.x * blockDim.x + threadIdx.x;
    if (e < E) g_ew[e] = g_dinv[__ldg(src + e)] * g_dinv[__ldg(dst + e)];
}

// ---------------- dense: HR[100000,64] = x[100000,512] @ W1[512,64] --------------
// 128 threads, block tile 128x64, thread tile 8x8, packed fma.rn.f32x2 math.
#define GBM 128
#define GBK 16
__global__ void __launch_bounds__(128, 4) gemm1_kernel(const float* __restrict__ x) {
    __shared__ float As[GBK][GBM];           // [k][m]
    __shared__ float Bs[GBK][64];            // [k][n]
    int tid = threadIdx.x;                   // 128 threads
    int tx = tid & 7, ty = tid >> 3;         // 8 col-groups x 16 row-groups
    int brow = blockIdx.x * GBM;

    unsigned long long acc[8][4];            // [row i][col pair j]: (c=tx*8+2j, c+1)
#pragma unroll
    for (int i = 0; i < 8; i++)
#pragma unroll
        for (int j = 0; j < 4; j++) acc[i][j] = 0ull;

    for (int k0 = 0; k0 < NFEAT; k0 += GBK) {
        // A: 128 rows x 16 k. Each thread: 4 float4 (one row, 16 k's), transposed store.
        {
            int gr = brow + tid;
            bool ok = (gr < NN);
            const float* xp = ok ? &x[(size_t)gr * NFEAT + k0] : nullptr;
#pragma unroll
            for (int it = 0; it < 4; ++it) {
                float4 v = ok ? *(const float4*)(xp + it * 4)
                              : make_float4(0.f, 0.f, 0.f, 0.f);
                As[it * 4 + 0][tid] = v.x;
                As[it * 4 + 1][tid] = v.y;
                As[it * 4 + 2][tid] = v.z;
                As[it * 4 + 3][tid] = v.w;
            }
        }
        // B: 16 rows x 64 cols = 256 float4 / 128 threads.
#pragma unroll
        for (int it = 0; it < 2; ++it) {
            int q = tid + it * 128;
            int r = q >> 4, c4 = q & 15;
            *(float4*)&Bs[r][c4 * 4] = *(const float4*)&g_W1[(k0 + r) * 64 + c4 * 4];
        }
        __syncthreads();
#pragma unroll
        for (int kk = 0; kk < GBK; ++kk) {
            float a[8];
            *(float4*)&a[0] = *(const float4*)&As[kk][ty * 8];
            *(float4*)&a[4] = *(const float4*)&As[kk][ty * 8 + 4];
            unsigned long long ad[8];
#pragma unroll
            for (int i = 0; i < 8; i++) ad[i] = pack_dup(a[i]);
            unsigned long long bv[4];
#pragma unroll
            for (int j = 0; j < 4; j++)
                bv[j] = *(const unsigned long long*)&Bs[kk][tx * 8 + 2 * j];
#pragma unroll
            for (int i = 0; i < 8; i++)
#pragma unroll
                for (int j = 0; j < 4; j++) fma2(acc[i][j], ad[i], bv[j]);
        }
        __syncthreads();
    }
#pragma unroll
    for (int i = 0; i < 8; i++) {
        int gr = brow + ty * 8 + i;
        if (gr < NN) {
            float2 p0 = unpack2(acc[i][0]), p1 = unpack2(acc[i][1]);
            float2 p2 = unpack2(acc[i][2]), p3 = unpack2(acc[i][3]);
            *(float4*)&g_HR[(size_t)gr * 64 + tx * 8]     = make_float4(p0.x, p0.y, p1.x, p1.y);
            *(float4*)&g_HR[(size_t)gr * 64 + tx * 8 + 4] = make_float4(p2.x, p2.y, p3.x, p3.y);
        }
    }
}

// ---------------- layer-1 scatter: agg1[dst] += ew * HR[src, 0:32] ----------------
__global__ void edge1_kernel(const int* __restrict__ src, const int* __restrict__ dst, int E) {
    int idx = blockIdx.x * blockDim.x + threadIdx.x;
    if (idx >= E * 8) return;
    int e = idx >> 3, g = idx & 7;
    int s = __ldg(src + e), d = __ldg(dst + e);
    float w = g_ew[e];
    float4 v = *(const float4*)&g_HR[(size_t)s * 64 + g * 4];
    red_add_v4(&g_agg1[(size_t)d * 32 + g * 4], v.x * w, v.y * w, v.z * w, v.w * w);
}

// ---------------- layer-1 epilogue: h1 = mean_k relu(agg1 + x@rw1 + b1) -----------
__global__ void epi1_kernel(const float* __restrict__ b1, int nrows) {
    int i = blockIdx.x * blockDim.x + threadIdx.x;
    if (i >= nrows * HID) return;
    int n = i / HID, j = i - (i / HID) * HID;
    float a0 = g_agg1[(size_t)n * 32 + j]      + g_HR[(size_t)n * 64 + 32 + j] + b1[j];
    float a1 = g_agg1[(size_t)n * 32 + 16 + j] + g_HR[(size_t)n * 64 + 48 + j] + b1[16 + j];
    g_h1[i] = 0.5f * (fmaxf(a0, 0.f) + fmaxf(a1, 0.f));
}

// ---------------- layer-2 scatter (pre-transform): agg2[dst] += ew * h1[src] ------
__global__ void edge2_kernel(const int* __restrict__ src, const int* __restrict__ dst, int E) {
    int idx = blockIdx.x * blockDim.x + threadIdx.x;
    if (idx >= E * 4) return;
    int e = idx >> 2, g = idx & 3;
    int s = __ldg(src + e), d = __ldg(dst + e);
    float w = g_ew[e];
    float4 v = *(const float4*)&g_h1[s * HID + g * 4];
    red_add_v4(&g_agg2[d * HID + g * 4], v.x * w, v.y * w, v.z * w, v.w * w);
}

// ---------------- layer-2 transform + epilogue ------------------------------------
__global__ void out_kernel(const float* __restrict__ b2, float* __restrict__ out, int nrows) {
    __shared__ float Ws[HID * 160];
    int tid = threadIdx.x;                   // 320 threads: 8 nodes x 40 outputs
    for (int i = tid; i < HID * 160; i += 320) Ws[i] = g_W2[i];
    __syncthreads();
    int n = blockIdx.x * 8 + tid / 40;
    int o = tid - (tid / 40) * 40;
    if (n >= nrows) return;
    float a[HID], hv[HID];
#pragma unroll
    for (int f = 0; f < HID; ++f) {
        a[f]  = g_agg2[n * HID + f];
        hv[f] = g_h1[n * HID + f];
    }
    float acc0 = b2[o], acc1 = b2[40 + o];
#pragma unroll
    for (int f = 0; f < HID; ++f) {
        const float* wr = &Ws[f * 160];
        acc0 += a[f] * wr[o]      + hv[f] * wr[80 + o];
        acc1 += a[f] * wr[40 + o] + hv[f] * wr[120 + o];
    }
    out[n * 40 + o] = 0.5f * (fmaxf(acc0, 0.f) + fmaxf(acc1, 0.f));
}

// ---------------- launch ----------------
extern "C" void kernel_launch(void* const* d_in, const int* in_sizes, int n_in,
                              void* d_out, int out_size) {
    const float* x   = (const float*)d_in[0];
    const int*   ei  = (const int*)d_in[1];
    const float* iw1 = (const float*)d_in[2];
    const float* rw1 = (const float*)d_in[3];
    const float* b1  = (const float*)d_in[4];
    const float* iw2 = (const float*)d_in[5];
    const float* rw2 = (const float*)d_in[6];
    const float* b2  = (const float*)d_in[7];
    float* out = (float*)d_out;

    int E = in_sizes[1] / 2;
    const int* src = ei;
    const int* dst = ei + E;

    zero_kernel<<<(NN * 32 + 255) / 256, 256>>>();
    pack_w1<<<(NFEAT * 64 + 255) / 256, 256>>>(iw1, rw1);
    pack_w2<<<(HID * 160 + 255) / 256, 256>>>(iw2, rw2);
    deg_kernel<<<(E + 255) / 256, 256>>>(dst, E);
    dinv_kernel<<<(NN + 255) / 256, 256>>>();
    ew_kernel<<<(E + 255) / 256, 256>>>(src, dst, E);
    gemm1_kernel<<<(NN + GBM - 1) / GBM, 128>>>(x);
    edge1_kernel<<<(E * 8 + 255) / 256, 256>>>(src, dst, E);
    epi1_kernel<<<(NN * HID + 255) / 256, 256>>>(b1, NN);
    edge2_kernel<<<(E * 4 + 255) / 256, 256>>>(src, dst, E);
    out_kernel<<<(NN + 7) / 8, 320>>>(b2, out, NN);
}

// round 14
// speedup vs baseline: 2.1828x; 1.0475x over previous
#include <cuda_runtime.h>
#include <cstdint>

#define NN     100000
#define NFEAT  512
#define HID    16
#define NCLASS 40
#define EMAX   3200000

// ---------------- scratch (static device globals; no allocation) ----------------
__device__ float g_deg[NN];
__device__ float g_dinv[NN];
__device__ float g_ew[EMAX];
__device__ float g_W1[NFEAT * 64];          // packed [f][c]: c<32 -> iw1[k=c/16][f][c%16], c>=32 -> rw1
__device__ float g_HR[(size_t)NN * 64];     // [n][c]: c<32 = x@iw1 (k-major), c>=32 = x@rw1
__device__ float g_agg1[(size_t)NN * 32];   // scatter target layer 1
__device__ float g_h1[NN * HID];            // layer-1 output
__device__ float g_agg2[NN * HID];          // scatter target layer 2 (pre-transform)
__device__ float g_W2[HID * 160];           // packed [f][c]: c<80 -> iw2[k][f][c%40], c>=80 -> rw2

// ---------------- helpers ----------------
__device__ __forceinline__ void red_add_v4(float* p, float a, float b, float c, float d) {
    asm volatile("red.global.add.v4.f32 [%0], {%1,%2,%3,%4};"
                 :: "l"(p), "f"(a), "f"(b), "f"(c), "f"(d) : "memory");
}

// ---------------- setup kernels ----------------
__global__ void zero_kernel() {
    int i = blockIdx.x * blockDim.x + threadIdx.x;
    if (i < NN) g_deg[i] = 0.f;
    if (i < NN * 32) g_agg1[i] = 0.f;
    if (i < NN * 16) g_agg2[i] = 0.f;
}

__global__ void pack_w1(const float* __restrict__ iw1, const float* __restrict__ rw1) {
    int i = blockIdx.x * blockDim.x + threadIdx.x;
    if (i >= NFEAT * 64) return;
    int f = i >> 6, c = i & 63;
    float v;
    if (c < 32) { int k = c >> 4, j = c & 15; v = iw1[(k * NFEAT + f) * HID + j]; }
    else        { int c2 = c - 32; int k = c2 >> 4, j = c2 & 15; v = rw1[(k * NFEAT + f) * HID + j]; }
    g_W1[i] = v;
}

__global__ void pack_w2(const float* __restrict__ iw2, const float* __restrict__ rw2) {
    int i = blockIdx.x * blockDim.x + threadIdx.x;
    if (i >= HID * 160) return;
    int f = i / 160, c = i % 160;
    float v;
    if (c < 80) { int k = c / 40, o = c % 40; v = iw2[(k * HID + f) * NCLASS + o]; }
    else        { int c2 = c - 80; int k = c2 / 40, o = c2 % 40; v = rw2[(k * HID + f) * NCLASS + o]; }
    g_W2[i] = v;
}

__global__ void deg_kernel(const int* __restrict__ dst, int E) {
    int e = blockIdx.x * blockDim.x + threadIdx.x;
    if (e < E) atomicAdd(&g_deg[__ldg(dst + e)], 1.0f);
}

__global__ void dinv_kernel() {
    int n = blockIdx.x * blockDim.x + threadIdx.x;
    if (n < NN) { float d = g_deg[n]; g_dinv[n] = (d > 0.f) ? rsqrtf(d) : 0.f; }
}

__global__ void ew_kernel(const int* __restrict__ src, const int* __restrict__ dst, int E) {
    int e = blockIdx.x * blockDim.x + threadIdx.x;
    if (e < E) g_ew[e] = g_dinv[__ldg(src + e)] * g_dinv[__ldg(dst + e)];
}

// ---------------- dense: HR[100000,64] = x[100000,512] @ W1[512,64] --------------
// R2 proven tiling: 256 threads, block tile 128x64, thread tile 8x4.
#define BM 128
#define BK 16
__global__ void gemm1_kernel(const float* __restrict__ x, int nrows) {
    __shared__ float As[BK][BM + 4];         // [k][m], padded
    __shared__ float Bs[BK][64];             // [k][n]
    int tid = threadIdx.x;                   // 256 threads
    int tx = tid & 15, ty = tid >> 4;        // 16 x 16
    int brow = blockIdx.x * BM;
    float acc[8][4];
#pragma unroll
    for (int i = 0; i < 8; i++)
#pragma unroll
        for (int j = 0; j < 4; j++) acc[i][j] = 0.f;

    for (int k0 = 0; k0 < NFEAT; k0 += BK) {
#pragma unroll
        for (int it = 0; it < 2; ++it) {     // A: 128x16 = 512 float4
            int q = tid + it * 256;
            int row = q >> 2, c4 = q & 3;
            int gr = brow + row;
            float4 v = make_float4(0.f, 0.f, 0.f, 0.f);
            if (gr < nrows) v = *(const float4*)&x[(size_t)gr * NFEAT + k0 + c4 * 4];
            As[c4 * 4 + 0][row] = v.x;
            As[c4 * 4 + 1][row] = v.y;
            As[c4 * 4 + 2][row] = v.z;
            As[c4 * 4 + 3][row] = v.w;
        }
        {                                     // B: 16x64 = 256 float4
            int row = tid >> 4, c4 = tid & 15;
            *(float4*)&Bs[row][c4 * 4] = *(const float4*)&g_W1[(k0 + row) * 64 + c4 * 4];
        }
        __syncthreads();
#pragma unroll
        for (int kk = 0; kk < BK; ++kk) {
            float a[8], b[4];
            *(float4*)&a[0] = *(const float4*)&As[kk][ty * 8];
            *(float4*)&a[4] = *(const float4*)&As[kk][ty * 8 + 4];
            *(float4*)&b[0] = *(const float4*)&Bs[kk][tx * 4];
#pragma unroll
            for (int i = 0; i < 8; i++)
#pragma unroll
                for (int j = 0; j < 4; j++) acc[i][j] += a[i] * b[j];
        }
        __syncthreads();
    }
#pragma unroll
    for (int i = 0; i < 8; i++) {
        int gr = brow + ty * 8 + i;
        if (gr < nrows)
            *(float4*)&g_HR[(size_t)gr * 64 + tx * 4] =
                make_float4(acc[i][0], acc[i][1], acc[i][2], acc[i][3]);
    }
}

// ---------------- layer-1 scatter: agg1[dst] += ew * HR[src, 0:32] ----------------
// 4 threads/edge, 8 floats each: 2 LDG.128 + 2 RED.128 per thread.
__global__ void edge1_kernel(const int* __restrict__ src, const int* __restrict__ dst, int E) {
    int idx = blockIdx.x * blockDim.x + threadIdx.x;
    if (idx >= E * 4) return;
    int e = idx >> 2, g = idx & 3;
    int s = __ldg(src + e), d = __ldg(dst + e);
    float w = g_ew[e];
    const float* hp = &g_HR[(size_t)s * 64 + g * 8];
    float4 v0 = *(const float4*)(hp);
    float4 v1 = *(const float4*)(hp + 4);
    float* ap = &g_agg1[(size_t)d * 32 + g * 8];
    red_add_v4(ap,     v0.x * w, v0.y * w, v0.z * w, v0.w * w);
    red_add_v4(ap + 4, v1.x * w, v1.y * w, v1.z * w, v1.w * w);
}

// ---------------- layer-1 epilogue: h1 = mean_k relu(agg1 + x@rw1 + b1) -----------
__global__ void epi1_kernel(const float* __restrict__ b1, int nrows) {
    int i = blockIdx.x * blockDim.x + threadIdx.x;
    if (i >= nrows * HID) return;
    int n = i / HID, j = i - (i / HID) * HID;
    float a0 = g_agg1[(size_t)n * 32 + j]      + g_HR[(size_t)n * 64 + 32 + j] + b1[j];
    float a1 = g_agg1[(size_t)n * 32 + 16 + j] + g_HR[(size_t)n * 64 + 48 + j] + b1[16 + j];
    g_h1[i] = 0.5f * (fmaxf(a0, 0.f) + fmaxf(a1, 0.f));
}

// ---------------- layer-2 scatter (pre-transform): agg2[dst] += ew * h1[src] ------
// 2 threads/edge, 8 floats each: 2 LDG.128 + 2 RED.128 per thread.
__global__ void edge2_kernel(const int* __restrict__ src, const int* __restrict__ dst, int E) {
    int idx = blockIdx.x * blockDim.x + threadIdx.x;
    if (idx >= E * 2) return;
    int e = idx >> 1, g = idx & 1;
    int s = __ldg(src + e), d = __ldg(dst + e);
    float w = g_ew[e];
    const float* hp = &g_h1[s * HID + g * 8];
    float4 v0 = *(const float4*)(hp);
    float4 v1 = *(const float4*)(hp + 4);
    float* ap = &g_agg2[d * HID + g * 8];
    red_add_v4(ap,     v0.x * w, v0.y * w, v0.z * w, v0.w * w);
    red_add_v4(ap + 4, v1.x * w, v1.y * w, v1.z * w, v1.w * w);
}

// ---------------- layer-2 transform + epilogue ------------------------------------
__global__ void out_kernel(const float* __restrict__ b2, float* __restrict__ out, int nrows) {
    __shared__ float Ws[HID * 160];
    int tid = threadIdx.x;                   // 320 threads: 8 nodes x 40 outputs
    for (int i = tid; i < HID * 160; i += 320) Ws[i] = g_W2[i];
    __syncthreads();
    int n = blockIdx.x * 8 + tid / 40;
    int o = tid - (tid / 40) * 40;
    if (n >= nrows) return;
    float a[HID], hv[HID];
#pragma unroll
    for (int f = 0; f < HID; ++f) {
        a[f]  = g_agg2[n * HID + f];
        hv[f] = g_h1[n * HID + f];
    }
    float acc0 = b2[o], acc1 = b2[40 + o];
#pragma unroll
    for (int f = 0; f < HID; ++f) {
        const float* wr = &Ws[f * 160];
        acc0 += a[f] * wr[o]      + hv[f] * wr[80 + o];
        acc1 += a[f] * wr[40 + o] + hv[f] * wr[120 + o];
    }
    out[n * 40 + o] = 0.5f * (fmaxf(acc0, 0.f) + fmaxf(acc1, 0.f));
}

// ---------------- launch ----------------
extern "C" void kernel_launch(void* const* d_in, const int* in_sizes, int n_in,
                              void* d_out, int out_size) {
    const float* x   = (const float*)d_in[0];
    const int*   ei  = (const int*)d_in[1];
    const float* iw1 = (const float*)d_in[2];
    const float* rw1 = (const float*)d_in[3];
    const float* b1  = (const float*)d_in[4];
    const float* iw2 = (const float*)d_in[5];
    const float* rw2 = (const float*)d_in[6];
    const float* b2  = (const float*)d_in[7];
    float* out = (float*)d_out;

    int E = in_sizes[1] / 2;
    const int* src = ei;
    const int* dst = ei + E;

    // Reordered: gemm1 moved to launch slot 4 (the slot ncu keeps profiling)
    // so next round's roofline shows the dense kernel. Deps still hold:
    // gemm1 needs only pack_w1; edge1 needs gemm1 + ew.
    zero_kernel<<<(NN * 32 + 255) / 256, 256>>>();
    pack_w1<<<(NFEAT * 64 + 255) / 256, 256>>>(iw1, rw1);
    pack_w2<<<(HID * 160 + 255) / 256, 256>>>(iw2, rw2);
    gemm1_kernel<<<(NN + BM - 1) / BM, 256>>>(x, NN);
    deg_kernel<<<(E + 255) / 256, 256>>>(dst, E);
    dinv_kernel<<<(NN + 255) / 256, 256>>>();
    ew_kernel<<<(E + 255) / 256, 256>>>(src, dst, E);
    edge1_kernel<<<(E * 4 + 255) / 256, 256>>>(src, dst, E);
    epi1_kernel<<<(NN * HID + 255) / 256, 256>>>(b1, NN);
    edge2_kernel<<<(E * 2 + 255) / 256, 256>>>(src, dst, E);
    out_kernel<<<(NN + 7) / 8, 320>>>(b2, out, NN);
}